// round 5
// baseline (speedup 1.0000x reference)
#include <cuda_runtime.h>
#include <math.h>

// ---------------------------------------------------------------------------
// MS-SSIM + L1 loss — fused separable-Gaussian tile kernel.
// All convolutions FFMA2-packed; double-buffered tmp (tA/tB) software-pipelines
// {v-pass i, h-pass i+1} per barrier phase.
//
// Pass inventory per 64x64 tile (h over 96 rows, v over 64):
//  c0: (x,x2)s0 r3, (y,y2)s0 r3, (x,x2)s1 r6, (y,y2)s1 r6, (xy@s0,xy@s1) r6
//  c1: (x,x2)s1, (y,y2)s1, (x,x2)s2 r11, (y,y2)s2, (xy@s1,xy@s2) r11,
//      (x,x2)s3 r16, (y,y2)s3, (xy@s3, L1@s4) r16
//  c2: (x,x2)s3, (y,y2)s3, (x,x2)s4, (y,y2)s4, (xy@s3,xy@s4) r16,
//      (L1_c0@s4, L1_c2@s4) r16   [needs |x-y| plane of c0 kept in smem]
// ---------------------------------------------------------------------------

typedef unsigned long long u64;

#define W2 97     // slab row stride (floats); 97 % 32 == 1 -> conflict-free
#define WTU 65    // packed tmp row stride (u64)
#define SMEM_BYTES (3 * 96 * W2 * 4 + 2 * 96 * WTU * 8)   // 211584

__device__ float g_g1d[5 * 33];
__device__ float g_partLoss[512];
__device__ float g_partL1[512];

__global__ void initCoefs(const float* __restrict__ gm) {
    int t = threadIdx.x;
    if (t < 165) {
        int s = t / 33, i = t % 33;
        g_g1d[t] = sqrtf(fmaxf(gm[(3 * s) * 1089 + i * 34], 0.0f));
    }
}

// ---------------------------------------------------------------------------
__device__ __forceinline__ u64 pk2(float lo, float hi) {
    u64 r; asm("mov.b64 %0, {%1, %2};" : "=l"(r) : "f"(lo), "f"(hi)); return r;
}
__device__ __forceinline__ void upk2(u64 v, float& lo, float& hi) {
    asm("mov.b64 {%0, %1}, %2;" : "=f"(lo), "=f"(hi) : "l"(v));
}
__device__ __forceinline__ u64 ffma2(u64 a, u64 b, u64 c) {
    u64 d; asm("fma.rn.f32x2 %0, %1, %2, %3;" : "=l"(d) : "l"(a), "l"(b), "l"(c));
    return d;
}

// w-element builders per MODE
template <int MODE>
__device__ __forceinline__ u64 mkw(const float* pa, const float* pb,
                                   const float* pc, int o) {
    if (MODE == 0) { float f = pa[o]; return pk2(f, f * f); }
    if (MODE == 1) { float v = pa[o] * pb[o]; return pk2(v, v); }
    if (MODE == 2) { float xv = pa[o], yv = pb[o];
                     return pk2(xv * yv, fabsf(xv - yv)); }
    { float xv = pa[o], yv = pb[o]; return pk2(pc[o], fabsf(xv - yv)); }
}

// Horizontal packed conv: 768 slots = 96 rows x 8 col-groups of 8.
template <int RW, int MODE, bool SAMEG>
__device__ __forceinline__ void hpass2(const float* pa, const float* pb,
                                       const float* pc, u64* t,
                                       const float* __restrict__ gA,
                                       const float* __restrict__ gB, int tid) {
    for (int idx = tid; idx < 768; idx += 512) {
        int r = idx % 96, gq = idx / 96;
        int base = r * W2 + gq * 8 + (16 - RW);
        u64 acc[8], w[8];
#pragma unroll
        for (int j = 0; j < 8; j++) w[j] = mkw<MODE>(pa, pb, pc, base + j);
#pragma unroll
        for (int i = 0; i < 8; i++) acc[i] = 0ULL;
#pragma unroll
        for (int k = 0; k <= 2 * RW; k++) {
            float ga = __ldg(gA + k);
            float gb = SAMEG ? ga : __ldg(gB + k);
            u64 c2 = pk2(ga, gb);
#pragma unroll
            for (int i = 0; i < 8; i++) acc[i] = ffma2(c2, w[(k + i) & 7], acc[i]);
            if (k < 2 * RW) w[k & 7] = mkw<MODE>(pa, pb, pc, base + k + 8);
        }
        u64* ob = t + r * WTU + gq * 8;
#pragma unroll
        for (int i = 0; i < 8; i++) ob[i] = acc[i];
    }
}

// Vertical packed conv: 512 threads = 64 cols x 8 row-groups of 8.
template <int RW, bool SAMEG>
__device__ __forceinline__ void vpass2(const u64* t,
                                       const float* __restrict__ gA,
                                       const float* __restrict__ gB,
                                       int tx, int ty, u64 out[8]) {
    const u64* p = t + (ty * 8 + 16 - RW) * WTU + tx;
    u64 acc[8], w[8];
#pragma unroll
    for (int j = 0; j < 8; j++) w[j] = p[j * WTU];
#pragma unroll
    for (int i = 0; i < 8; i++) acc[i] = 0ULL;
#pragma unroll
    for (int k = 0; k <= 2 * RW; k++) {
        float ga = __ldg(gA + k);
        float gb = SAMEG ? ga : __ldg(gB + k);
        u64 c2 = pk2(ga, gb);
#pragma unroll
        for (int i = 0; i < 8; i++) acc[i] = ffma2(c2, w[(k + i) & 7], acc[i]);
        if (k < 2 * RW) w[k & 7] = p[(k + 8) * WTU];
    }
#pragma unroll
    for (int i = 0; i < 8; i++) out[i] = acc[i];
}

// ---------------------------------------------------------------------------
__global__ __launch_bounds__(512) void fusedK(const float* __restrict__ x,
                                              const float* __restrict__ y) {
    extern __shared__ float smem[];
    float* sx = smem;                     // 96 x W2
    float* sy = sx + 96 * W2;
    float* sL1 = sy + 96 * W2;            // |x-y| plane of channel 0
    u64* tA = (u64*)(sL1 + 96 * W2);      // 96 x WTU
    u64* tB = tA + 96 * WTU;

    int tid = threadIdx.x;
    int tx = tid & 63, ty = tid >> 6;
    int col0 = blockIdx.x * 64, row0 = blockIdx.y * 64, b = blockIdx.z;

    const float* g0 = g_g1d + 0 * 33;
    const float* g1 = g_g1d + 1 * 33;
    const float* g2 = g_g1d + 2 * 33;
    const float* g3 = g_g1d + 3 * 33;
    const float* g4 = g_g1d + 4 * 33;

    float prod[8], l1s[8];
#pragma unroll
    for (int i = 0; i < 8; i++) { prod[i] = 1.0f; l1s[i] = 0.0f; }
    float rawL1 = 0.0f;

    auto loadSlab = [&](int c, bool wL1) {
        const float* xp = x + (size_t)(b * 3 + c) * 262144;
        const float* yp = y + (size_t)(b * 3 + c) * 262144;
        for (int idx = tid; idx < 96 * 96; idx += 512) {
            int rr = idx / 96, cc = idx - rr * 96;
            int gr = row0 - 16 + rr, gc = col0 - 16 + cc;
            float xv = 0.0f, yv = 0.0f;
            if (gr >= 0 && gr < 512 && gc >= 0 && gc < 512) {
                xv = fmaf(xp[gr * 512 + gc], 0.5f, 0.5f);
                yv = fmaf(yp[gr * 512 + gc], 0.5f, 0.5f);
            }
            sx[rr * W2 + cc] = xv;
            sy[rr * W2 + cc] = yv;
            float ad = fabsf(xv - yv);
            if (wL1) sL1[rr * W2 + cc] = ad;
            if (rr >= 16 && rr < 80 && cc >= 16 && cc < 80) rawL1 += ad;
        }
    };

    // fold (mu,E) pairs -> (t1 = C2 - 2*mxy, S = sxx+syy+C2); lm applies l^3.
    auto fold = [&](const u64* ox, const u64* oy, float* t1, float* S, bool lm) {
#pragma unroll
        for (int i = 0; i < 8; i++) {
            float mux, ex2, muy, ey2;
            upk2(ox[i], mux, ex2);
            upk2(oy[i], muy, ey2);
            float m2x = mux * mux, m2y = muy * muy, mxy = mux * muy;
            t1[i] = 9.0e-4f - 2.0f * mxy;
            S[i] = (ex2 - m2x) + (ey2 - m2y) + 9.0e-4f;
            if (lm) {
                float l = __fdividef(2.0f * mxy + 1.0e-4f, m2x + m2y + 1.0e-4f);
                prod[i] *= l * l * l;
            }
        }
    };
    // apply cs^mult for packed exy pair (lane lo = combo a, hi = combo b)
    auto csPair = [&](const u64* e, const float* t1a, const float* Sa, int ma,
                      const float* t1b, const float* Sb, int mb) {
#pragma unroll
        for (int i = 0; i < 8; i++) {
            float ea, eb;
            upk2(e[i], ea, eb);
            float ca = __fdividef(2.0f * ea + t1a[i], Sa[i]);
            float cb = __fdividef(2.0f * eb + t1b[i], Sb[i]);
            float pa = ca; if (ma >= 2) pa *= ca; if (ma >= 3) pa *= ca;
            float pb = cb; if (mb >= 2) pb *= cb; if (mb >= 3) pb *= cb;
            prod[i] *= pa * pb;
        }
    };

    u64 ox[8], oy[8], ev[8];
    float t1a[8], Sa[8], t1b[8], Sb[8];

    // ======================= channel 0 =======================
    loadSlab(0, true);
    __syncthreads();
    hpass2<3, 0, true>(sx, 0, 0, tA, g0 + 13, g0 + 13, tid);
    __syncthreads();
    vpass2<3, true>(tA, g0 + 13, g0 + 13, tx, ty, ox);
    hpass2<3, 0, true>(sy, 0, 0, tB, g0 + 13, g0 + 13, tid);
    __syncthreads();
    vpass2<3, true>(tB, g0 + 13, g0 + 13, tx, ty, oy);
    fold(ox, oy, t1a, Sa, false);                            // s0 @ c0
    hpass2<6, 0, true>(sx, 0, 0, tA, g1 + 10, g1 + 10, tid);
    __syncthreads();
    vpass2<6, true>(tA, g1 + 10, g1 + 10, tx, ty, ox);
    hpass2<6, 0, true>(sy, 0, 0, tB, g1 + 10, g1 + 10, tid);
    __syncthreads();
    vpass2<6, true>(tB, g1 + 10, g1 + 10, tx, ty, oy);
    fold(ox, oy, t1b, Sb, false);                            // s1 @ c0
    hpass2<6, 1, false>(sx, sy, 0, tA, g0 + 10, g1 + 10, tid);
    __syncthreads();
    vpass2<6, false>(tA, g0 + 10, g1 + 10, tx, ty, ev);
    csPair(ev, t1a, Sa, 3, t1b, Sb, 2);
    loadSlab(1, false);
    __syncthreads();

    // ======================= channel 1 =======================
    hpass2<6, 0, true>(sx, 0, 0, tB, g1 + 10, g1 + 10, tid);
    __syncthreads();
    vpass2<6, true>(tB, g1 + 10, g1 + 10, tx, ty, ox);
    hpass2<6, 0, true>(sy, 0, 0, tA, g1 + 10, g1 + 10, tid);
    __syncthreads();
    vpass2<6, true>(tA, g1 + 10, g1 + 10, tx, ty, oy);
    fold(ox, oy, t1a, Sa, false);                            // s1 @ c1
    hpass2<11, 0, true>(sx, 0, 0, tB, g2 + 5, g2 + 5, tid);
    __syncthreads();
    vpass2<11, true>(tB, g2 + 5, g2 + 5, tx, ty, ox);
    hpass2<11, 0, true>(sy, 0, 0, tA, g2 + 5, g2 + 5, tid);
    __syncthreads();
    vpass2<11, true>(tA, g2 + 5, g2 + 5, tx, ty, oy);
    fold(ox, oy, t1b, Sb, false);                            // s2 @ c1
    hpass2<11, 1, false>(sx, sy, 0, tB, g1 + 5, g2 + 5, tid);
    __syncthreads();
    vpass2<11, false>(tB, g1 + 5, g2 + 5, tx, ty, ev);
    csPair(ev, t1a, Sa, 1, t1b, Sb, 3);
    hpass2<16, 0, true>(sx, 0, 0, tA, g3, g3, tid);
    __syncthreads();
    vpass2<16, true>(tA, g3, g3, tx, ty, ox);
    hpass2<16, 0, true>(sy, 0, 0, tB, g3, g3, tid);
    __syncthreads();
    vpass2<16, true>(tB, g3, g3, tx, ty, oy);
    fold(ox, oy, t1a, Sa, false);                            // s3 @ c1
    hpass2<16, 2, false>(sx, sy, 0, tA, g3, g4, tid);        // (xy@s3, L1@s4)
    __syncthreads();
    vpass2<16, false>(tA, g3, g4, tx, ty, ev);
#pragma unroll
    for (int i = 0; i < 8; i++) {
        float ea, lb;
        upk2(ev[i], ea, lb);
        prod[i] *= __fdividef(2.0f * ea + t1a[i], Sa[i]);    // cs(s3,c1)^1
        l1s[i] += lb;                                        // L1 @ c1
    }
    loadSlab(2, false);
    __syncthreads();

    // ======================= channel 2 =======================
    hpass2<16, 0, true>(sx, 0, 0, tB, g3, g3, tid);
    __syncthreads();
    vpass2<16, true>(tB, g3, g3, tx, ty, ox);
    hpass2<16, 0, true>(sy, 0, 0, tA, g3, g3, tid);
    __syncthreads();
    vpass2<16, true>(tA, g3, g3, tx, ty, oy);
    fold(ox, oy, t1a, Sa, false);                            // s3 @ c2
    hpass2<16, 0, true>(sx, 0, 0, tB, g4, g4, tid);
    __syncthreads();
    vpass2<16, true>(tB, g4, g4, tx, ty, ox);
    hpass2<16, 0, true>(sy, 0, 0, tA, g4, g4, tid);
    __syncthreads();
    vpass2<16, true>(tA, g4, g4, tx, ty, oy);
    fold(ox, oy, t1b, Sb, true);                             // s4 @ c2 + l^3
    hpass2<16, 1, false>(sx, sy, 0, tB, g3, g4, tid);        // (xy@s3, xy@s4)
    __syncthreads();
    vpass2<16, false>(tB, g3, g4, tx, ty, ev);
    csPair(ev, t1a, Sa, 2, t1b, Sb, 3);
    hpass2<16, 3, true>(sx, sy, sL1, tA, g4, g4, tid);       // (L1_c0, L1_c2)
    __syncthreads();
    vpass2<16, true>(tA, g4, g4, tx, ty, ev);
#pragma unroll
    for (int i = 0; i < 8; i++) {
        float la, lc;
        upk2(ev[i], la, lc);
        l1s[i] += la + lc;
    }

    // ======================= epilogue =======================
    float tsum = 0.0f;
#pragma unroll
    for (int i = 0; i < 8; i++) {
        float ms = 1.0f - prod[i];
        float mix = 200.0f * (0.025f * ms + 0.975f * (l1s[i] * (1.0f / 3.0f)));
        tsum += mix;
    }

    __syncthreads();
    float* r1 = (float*)tA;
    float* r2 = r1 + 512;
    r1[tid] = tsum;
    r2[tid] = rawL1;
    __syncthreads();
    for (int s = 256; s > 0; s >>= 1) {
        if (tid < s) { r1[tid] += r1[tid + s]; r2[tid] += r2[tid + s]; }
        __syncthreads();
    }
    if (tid == 0) {
        int bid = (blockIdx.z * 8 + blockIdx.y) * 8 + blockIdx.x;
        g_partLoss[bid] = r1[0];
        g_partL1[bid] = r2[0];
    }
}

// ---------------------------------------------------------------------------
__global__ void finalK(float* out, const float* __restrict__ disc, int ndisc) {
    int tid = threadIdx.x;
    float ms = 0.0f;
    for (int i = tid; i < ndisc; i += 256) {
        float v = disc[i] - 1.0f;
        ms = fmaf(v, v, ms);
    }
    double s1 = 0.0, s2 = 0.0;
    for (int i = tid; i < 512; i += 256) {
        s1 += (double)g_partLoss[i];
        s2 += (double)g_partL1[i];
    }
    __shared__ double r1[256], r2[256];
    __shared__ float r3[256];
    r1[tid] = s1; r2[tid] = s2; r3[tid] = ms;
    __syncthreads();
    for (int s = 128; s > 0; s >>= 1) {
        if (tid < s) {
            r1[tid] += r1[tid + s];
            r2[tid] += r2[tid + s];
            r3[tid] += r3[tid + s];
        }
        __syncthreads();
    }
    if (tid == 0) {
        double lossMixMean = r1[0] / 2097152.0;     // 8*512*512
        double l1Mean = r2[0] / 6291456.0;          // 8*3*512*512
        double mseMean = (double)r3[0] / (double)ndisc;
        out[0] = (float)((lossMixMean + 100.0 * l1Mean + mseMean) * 0.5);
    }
}

// ---------------------------------------------------------------------------
extern "C" void kernel_launch(void* const* d_in, const int* in_sizes, int n_in,
                              void* d_out, int out_size) {
    const float* x = (const float*)d_in[0];
    const float* y = (const float*)d_in[1];
    const float* disc = (const float*)d_in[2];
    const float* gm = (const float*)d_in[3];
    int ndisc = in_sizes[2];

    cudaFuncSetAttribute(fusedK, cudaFuncAttributeMaxDynamicSharedMemorySize,
                         SMEM_BYTES);
    initCoefs<<<1, 192>>>(gm);
    fusedK<<<dim3(8, 8, 8), 512, SMEM_BYTES>>>(x, y);
    finalK<<<1, 256>>>((float*)d_out, disc, ndisc);
}